// round 16
// baseline (speedup 1.0000x reference)
#include <cuda_runtime.h>
#include <math.h>
#include <stdint.h>

#define Bn 64
#define Ln 2048
#define Hn 128
#define Vn 32000

// ---------------- scratch (static device globals; no runtime allocation) ----
__device__ float  g_ff1[(size_t)Vn * 256];
__device__ float  g_x  [(size_t)Vn * Hn];
__device__ float  g_hn [(size_t)Vn * Hn];
__device__ float  g_kt [(size_t)Vn * Hn];
__device__ float  g_kn [(size_t)Vn * Hn];
__device__ float2 g_meta[Vn];            // (norm, ||kn||^2)
__device__ float  g_read[Bn * Hn];
__device__ float  g_tmp [Bn * Hn];
__device__ float  g_zero[256];           // zero-initialized: dummy bias
// cross-CTA partials exchange: [batch][slot 2][entry 16] of {e, tag, pd, tag}
__device__ uint4  g_xch[Bn * 32];

// packed fp32x2 FMA
__device__ __forceinline__ float2 ffma2(float2 a, float2 b, float2 c) {
    float2 d;
    asm("fma.rn.f32x2 %0, %1, %2, %3;"
        : "=l"(reinterpret_cast<unsigned long long&>(d))
        : "l"(reinterpret_cast<unsigned long long&>(a)),
          "l"(reinterpret_cast<unsigned long long&>(b)),
          "l"(reinterpret_cast<unsigned long long&>(c)));
    return d;
}

// async global->shared copies
__device__ __forceinline__ void cp_async16(void* sdst, const void* gsrc) {
    uint32_t sa = (uint32_t)__cvta_generic_to_shared(sdst);
    asm volatile("cp.async.cg.shared.global [%0], [%1], 16;" :: "r"(sa), "l"(gsrc));
}
__device__ __forceinline__ void cp_async8(void* sdst, const void* gsrc) {
    uint32_t sa = (uint32_t)__cvta_generic_to_shared(sdst);
    asm volatile("cp.async.ca.shared.global [%0], [%1], 8;" :: "r"(sa), "l"(gsrc));
}

// volatile 16B global ld/st (single 16B transaction; L1-bypassing)
__device__ __forceinline__ uint4 ldg_v16(const uint4* p) {
    uint4 v;
    asm volatile("ld.volatile.global.v4.u32 {%0,%1,%2,%3}, [%4];"
        : "=r"(v.x), "=r"(v.y), "=r"(v.z), "=r"(v.w) : "l"(p) : "memory");
    return v;
}
__device__ __forceinline__ void stg_v16(uint4* p, uint4 v) {
    asm volatile("st.volatile.global.v4.u32 [%0], {%1,%2,%3,%4};"
        :: "l"(p), "r"(v.x), "r"(v.y), "r"(v.z), "r"(v.w) : "memory");
}

// ---------------- generic fp32 GEMM, conflict-free B reads (R15 winner) ------
template <bool RELU, bool RESID>
__global__ void __launch_bounds__(256, 2) sgemm_tn(
    const float* __restrict__ A, const float* __restrict__ Bm,
    const float* __restrict__ bias, const float* __restrict__ resid,
    float* __restrict__ C, int Nn, int K)
{
    __shared__ float As[32][132];
    __shared__ float Bs[32][132];
    const int m0 = blockIdx.x * 128;
    const int n0 = blockIdx.y * 128;
    const int tid = threadIdx.x;
    const int tx = tid & 15;
    const int ty = tid >> 4;
    const int lrow = tid >> 3;
    const int lk   = (tid & 7) * 4;

    float2 acc2[8][4];
#pragma unroll
    for (int i = 0; i < 8; ++i)
#pragma unroll
        for (int j = 0; j < 4; ++j) acc2[i][j] = make_float2(0.f, 0.f);

    for (int k0 = 0; k0 < K; k0 += 32) {
#pragma unroll
        for (int p = 0; p < 4; ++p) {
            int row = lrow + p * 32;
            float4 av = *(const float4*)&A [(size_t)(m0 + row) * K + k0 + lk];
            As[lk + 0][row] = av.x; As[lk + 1][row] = av.y;
            As[lk + 2][row] = av.z; As[lk + 3][row] = av.w;
            float4 bv = *(const float4*)&Bm[(size_t)(n0 + row) * K + k0 + lk];
            Bs[lk + 0][row] = bv.x; Bs[lk + 1][row] = bv.y;
            Bs[lk + 2][row] = bv.z; Bs[lk + 3][row] = bv.w;
        }
        __syncthreads();
#pragma unroll 8
        for (int kk = 0; kk < 32; ++kk) {
            float4 a0 = *(const float4*)&As[kk][ty * 8];
            float4 a1 = *(const float4*)&As[kk][ty * 8 + 4];
            float a[8] = {a0.x, a0.y, a0.z, a0.w, a1.x, a1.y, a1.z, a1.w};
            float b[8];
#pragma unroll
            for (int j = 0; j < 8; ++j) b[j] = Bs[kk][tx + 16 * j];
            float2 bb[4] = {make_float2(b[0], b[1]), make_float2(b[2], b[3]),
                            make_float2(b[4], b[5]), make_float2(b[6], b[7])};
#pragma unroll
            for (int i = 0; i < 8; ++i) {
                float2 ai = make_float2(a[i], a[i]);
#pragma unroll
                for (int j = 0; j < 4; ++j)
                    acc2[i][j] = ffma2(ai, bb[j], acc2[i][j]);
            }
        }
        __syncthreads();
    }

#pragma unroll
    for (int i = 0; i < 8; ++i) {
        const int m = m0 + ty * 8 + i;
#pragma unroll
        for (int j = 0; j < 4; ++j) {
            const int nx = n0 + tx + 32 * j;
            const int ny = nx + 16;
            float vx = acc2[i][j].x + bias[nx];
            float vy = acc2[i][j].y + bias[ny];
            if (RELU) { vx = fmaxf(vx, 0.f); vy = fmaxf(vy, 0.f); }
            if (RESID) {
                vx += resid[(size_t)m * Nn + nx];
                vy += resid[(size_t)m * Nn + ny];
            }
            C[(size_t)m * Nn + nx] = vx;
            C[(size_t)m * Nn + ny] = vy;
        }
    }
}

// ---------------- LayerNorm ---------------------------------------------------
__global__ void __launch_bounds__(256) ln_kernel(
    const float* __restrict__ g, const float* __restrict__ bparm)
{
    const int lane = threadIdx.x & 31;
    const int row  = blockIdx.x * 8 + (threadIdx.x >> 5);
    float4 v = ((const float4*)(g_x + (size_t)row * Hn))[lane];
    float s = (v.x + v.y) + (v.z + v.w);
#pragma unroll
    for (int d = 16; d; d >>= 1) s += __shfl_xor_sync(0xffffffffu, s, d);
    const float mu = s * (1.0f / 128.0f);
    float dx = v.x - mu, dy = v.y - mu, dz = v.z - mu, dw = v.w - mu;
    float q = (dx * dx + dy * dy) + (dz * dz + dw * dw);
#pragma unroll
    for (int d = 16; d; d >>= 1) q += __shfl_xor_sync(0xffffffffu, q, d);
    const float rstd = rsqrtf(q * (1.0f / 128.0f) + 1e-5f);
    float4 gg = ((const float4*)g)[lane];
    float4 bb = ((const float4*)bparm)[lane];
    float4 o;
    o.x = fmaf(dx * rstd, gg.x, bb.x);
    o.y = fmaf(dy * rstd, gg.y, bb.y);
    o.z = fmaf(dz * rstd, gg.z, bb.z);
    o.w = fmaf(dw * rstd, gg.w, bb.w);
    ((float4*)(g_hn + (size_t)row * Hn))[lane] = o;
}

// ---------------- row normalize k-table ---------------------------------------
__global__ void __launch_bounds__(256) norm_kernel()
{
    const int lane = threadIdx.x & 31;
    const int row  = blockIdx.x * 8 + (threadIdx.x >> 5);
    float4 v = ((const float4*)(g_kt + (size_t)row * Hn))[lane];
    float q = (v.x * v.x + v.y * v.y) + (v.z * v.z + v.w * v.w);
#pragma unroll
    for (int d = 16; d; d >>= 1) q += __shfl_xor_sync(0xffffffffu, q, d);
    const float nrm = sqrtf(q);
    const float den = fmaxf(nrm, 1e-12f);
    const float inv = 1.0f / den;
    float4 o; o.x = v.x * inv; o.y = v.y * inv; o.z = v.z * inv; o.w = v.w * inv;
    ((float4*)(g_kn + (size_t)row * Hn))[lane] = o;
    if (lane == 0) g_meta[row] = make_float2(nrm, q * inv * inv);
}

// ---------------- paired-CTA scan: 2 plain CTAs per batch --------------------
// Block 2b+rank owns rows [rank*64, rank*64+64). Thread=(r_loc=tid>>2, q=tid&3)
// holds 32 cols (16 float2) of M. Pipelined gate (R12 algebra, 3x validated):
//   vp_T = M_{T-2}.kn_T + g_{T-1}*rr_{T-1}*(kn_{T-1}.kn_T)
// (e,pd) warp partials (16 global entries) exchanged via a 2-slot L2 seqlock:
// lane0 of warp w publishes entry rank*8+w with tag T+1 duplicated in both 8B
// halves; every lane reads entry lane&15 (prefetched pre-barrier, validated
// next step). Identical 4-level shuffle tree on both CTAs -> bitwise-identical
// gates. 128 blocks < 148 SMs -> pair always co-resident -> spin is safe.
#define CSTEP(T, KP) do {                                                       \
    const int ns_ = ((T) + 1) & 7;                                              \
    /* validate prefetched partials(T-1): both tag halves == T */               \
    {                                                                           \
        bool ok_ = (pf.y == (uint32_t)(T)) && (pf.w == (uint32_t)(T));          \
        while (!__all_sync(0xffffffffu, ok_)) {                                 \
            pf = ldg_v16(xch + (((T) - 1) & 1) * 16 + (lane & 15));             \
            ok_ = (pf.y == (uint32_t)(T)) && (pf.w == (uint32_t)(T));           \
        }                                                                       \
    }                                                                           \
    float te_ = __uint_as_float(pf.x), dc_ = __uint_as_float(pf.z);             \
    te_ += __shfl_xor_sync(0xffffffffu, te_, 1);                                \
    dc_ += __shfl_xor_sync(0xffffffffu, dc_, 1);                                \
    te_ += __shfl_xor_sync(0xffffffffu, te_, 2);                                \
    dc_ += __shfl_xor_sync(0xffffffffu, dc_, 2);                                \
    te_ += __shfl_xor_sync(0xffffffffu, te_, 4);                                \
    dc_ += __shfl_xor_sync(0xffffffffu, dc_, 4);                                \
    te_ += __shfl_xor_sync(0xffffffffu, te_, 8);                                \
    dc_ += __shfl_xor_sync(0xffffffffu, dc_, 8);                                \
    const bool g_ = te_ * meta_prev.y * (1.0f / 16384.0f) >= 0.4f;              \
    float vp_ = vp_acc;                                                         \
    if (g_) vp_ = fmaf(rr_prev, dc_, vp_);                                      \
    const float rr_ = fmaf(meta_cur.x, kvc, -vp_);                              \
    const float  kvn_      = s_kn[ns_][kvidx];                                  \
    const float2 meta_nxt_ = s_meta[ns_];                                       \
    float e_  = rr_ * rr_;                                                      \
    float pd_ = kvc * kvn_;                                                     \
    e_  += __shfl_xor_sync(0xffffffffu, e_,  4);                                \
    pd_ += __shfl_xor_sync(0xffffffffu, pd_, 4);                                \
    e_  += __shfl_xor_sync(0xffffffffu, e_,  8);                                \
    pd_ += __shfl_xor_sync(0xffffffffu, pd_, 8);                                \
    e_  += __shfl_xor_sync(0xffffffffu, e_,  16);                               \
    pd_ += __shfl_xor_sync(0xffffffffu, pd_, 16);                               \
    if (lane == 0)                                                              \
        stg_v16(xch + ((T) & 1) * 16 + gwid,                                    \
                make_uint4(__float_as_uint(e_), (uint32_t)((T) + 1),            \
                           __float_as_uint(pd_), (uint32_t)((T) + 1)));         \
    /* gated update with KP=kn_{T-1}; reload KP<-kn_{T+1}; matvec */            \
    if (g_) {                                                                   \
        const float2 rr2_ = make_float2(rr_prev, rr_prev);                      \
        _Pragma("unroll")                                                       \
        for (int j_ = 0; j_ < 16; ++j_) M2[j_] = ffma2(rr2_, KP[j_], M2[j_]);   \
    }                                                                           \
    _Pragma("unroll")                                                           \
    for (int j_ = 0; j_ < 8; ++j_) {                                            \
        float4 v_ = *(const float4*)(s_kn[ns_] + padoff + j_ * 4);              \
        KP[2 * j_]     = make_float2(v_.x, v_.y);                               \
        KP[2 * j_ + 1] = make_float2(v_.z, v_.w);                               \
    }                                                                           \
    float2 a0_ = make_float2(0.f, 0.f), a1_ = a0_, a2_ = a0_, a3_ = a0_;        \
    _Pragma("unroll")                                                           \
    for (int j_ = 0; j_ < 16; j_ += 4) {                                        \
        a0_ = ffma2(M2[j_ + 0], KP[j_ + 0], a0_);                               \
        a1_ = ffma2(M2[j_ + 1], KP[j_ + 1], a1_);                               \
        a2_ = ffma2(M2[j_ + 2], KP[j_ + 2], a2_);                               \
        a3_ = ffma2(M2[j_ + 3], KP[j_ + 3], a3_);                               \
    }                                                                           \
    float an_ = ((a0_.x + a0_.y) + (a1_.x + a1_.y))                             \
              + ((a2_.x + a2_.y) + (a3_.x + a3_.y));                            \
    an_ += __shfl_xor_sync(0xffffffffu, an_, 1);                                \
    an_ += __shfl_xor_sync(0xffffffffu, an_, 2);                                \
    if (tid < 32) {                                                             \
        if ((T) + 4 < Ln) {                                                     \
            const int pb_  = ((T) + 4) & 7;                                     \
            const int tok_ = s_seq[(T) + 4];                                    \
            cp_async16(&s_kn[pb_][(tid >> 3) * 36 + (tid & 7) * 4],             \
                       g_kn + (size_t)tok_ * Hn + tid * 4);                     \
            if (tid == 0) cp_async8(&s_meta[pb_], g_meta + tok_);               \
        }                                                                       \
        asm volatile("cp.async.commit_group;" ::: "memory");                    \
        asm volatile("cp.async.wait_group 2;" ::: "memory");                    \
    }                                                                           \
    /* prefetch partials(T) for next step (validated after the barrier) */      \
    pf = ldg_v16(xch + ((T) & 1) * 16 + (lane & 15));                           \
    __syncthreads();                                                            \
    rr_prev = rr_; kvc = kvn_;                                                  \
    meta_prev = meta_cur; meta_cur = meta_nxt_;                                 \
    vp_acc = an_;                                                               \
} while (0)

__global__ void __launch_bounds__(256, 1) scan_kernel(const int* __restrict__ seq)
{
    __shared__ __align__(16) float  s_kn[8][144];   // quarter q at offset q*36
    __shared__ __align__(16) float2 s_meta[8];
    __shared__ int   s_seq[Ln];

    const int tid  = threadIdx.x;
    const int b    = blockIdx.x >> 1;
    const int rank = blockIdx.x & 1;
    const int lane = tid & 31;
    const int wid  = tid >> 5;

    const int r_loc  = tid >> 2;
    const int q      = tid & 3;
    const int gr     = rank * 64 + r_loc;
    const int padoff = q * 36;
    const int kvidx  = (gr >> 5) * 36 + (gr & 31);
    const int gwid   = rank * 8 + wid;

    uint4* xch = g_xch + b * 32;

    for (int i = tid; i < Ln; i += 256) s_seq[i] = seq[(size_t)b * Ln + i];

    float2 M2[16];
#pragma unroll
    for (int j = 0; j < 16; ++j) M2[j] = make_float2(0.f, 0.f);
    __syncthreads();

    // prologue: sync-load ring slots 0..3 (full 128-float vectors), meta
    if (tid < 128) {
        int slot = tid >> 5, c = tid & 31;
        int tok = s_seq[slot];
        *(float4*)(s_kn[slot] + (c >> 3) * 36 + (c & 7) * 4) =
            ((const float4*)(g_kn + (size_t)tok * Hn))[c];
    }
    if (tid < 4) s_meta[tid] = g_meta[s_seq[tid]];
    __syncthreads();

    // ka <- kn_0, kb <- kn_1 (quarter slices)
    float2 ka[16], kb[16];
#pragma unroll
    for (int j = 0; j < 8; ++j) {
        float4 v0 = *(const float4*)(s_kn[0] + padoff + j * 4);
        float4 v1 = *(const float4*)(s_kn[1] + padoff + j * 4);
        ka[2 * j]     = make_float2(v0.x, v0.y);
        ka[2 * j + 1] = make_float2(v0.z, v0.w);
        kb[2 * j]     = make_float2(v1.x, v1.y);
        kb[2 * j + 1] = make_float2(v1.z, v1.w);
    }

    // step 0: M = 0 -> vp_0 = 0, rr_0 = norm_0 * kn_0[gr]; publish tag 1
    float2 m0 = s_meta[0], m1 = s_meta[1];
    const float kv0 = s_kn[0][kvidx];
    const float kv1 = s_kn[1][kvidx];
    const float rr0 = m0.x * kv0;
    uint4 pf;
    {
        float e  = rr0 * rr0;
        float pd = kv0 * kv1;
        e  += __shfl_xor_sync(0xffffffffu, e,  4);
        pd += __shfl_xor_sync(0xffffffffu, pd, 4);
        e  += __shfl_xor_sync(0xffffffffu, e,  8);
        pd += __shfl_xor_sync(0xffffffffu, pd, 8);
        e  += __shfl_xor_sync(0xffffffffu, e,  16);
        pd += __shfl_xor_sync(0xffffffffu, pd, 16);
        if (lane == 0)
            stg_v16(xch + gwid,
                    make_uint4(__float_as_uint(e), 1u, __float_as_uint(pd), 1u));
        // async slot-4 token + one committed group so wait_group 2 is benign
        if (tid < 32) {
            int tok = s_seq[4];
            cp_async16(&s_kn[4][(tid >> 3) * 36 + (tid & 7) * 4],
                       g_kn + (size_t)tok * Hn + tid * 4);
            if (tid == 0) cp_async8(&s_meta[4], g_meta + tok);
            asm volatile("cp.async.commit_group;" ::: "memory");
        }
        pf = ldg_v16(xch + (lane & 15));   // prefetch partials(0)
        __syncthreads();
    }

    float  rr_prev = rr0, kvc = kv1, vp_acc = 0.f;
    float2 meta_prev = m0, meta_cur = m1;

    // steps 1..2046: 1023 pairs (odd T -> KP=ka holds kn_{T-1}, even -> kb)
    for (int t = 1; t <= Ln - 3; t += 2) {
        CSTEP(t,     ka);
        CSTEP(t + 1, kb);
    }

    // epilogue: resolve gate of step Ln-2 (tag Ln-1); corrected vp is the read
    {
        const uint32_t exp = (uint32_t)(Ln - 1);
        bool ok = (pf.y == exp) && (pf.w == exp);
        while (!__all_sync(0xffffffffu, ok)) {
            pf = ldg_v16(xch + ((Ln - 2) & 1) * 16 + (lane & 15));
            ok = (pf.y == exp) && (pf.w == exp);
        }
        float te = __uint_as_float(pf.x), dc = __uint_as_float(pf.z);
        te += __shfl_xor_sync(0xffffffffu, te, 1);
        dc += __shfl_xor_sync(0xffffffffu, dc, 1);
        te += __shfl_xor_sync(0xffffffffu, te, 2);
        dc += __shfl_xor_sync(0xffffffffu, dc, 2);
        te += __shfl_xor_sync(0xffffffffu, te, 4);
        dc += __shfl_xor_sync(0xffffffffu, dc, 4);
        te += __shfl_xor_sync(0xffffffffu, te, 8);
        dc += __shfl_xor_sync(0xffffffffu, dc, 8);
        float vp = vp_acc;
        if (te * meta_prev.y * (1.0f / 16384.0f) >= 0.4f)
            vp = fmaf(rr_prev, dc, vp);
        if (q == 0) g_read[b * Hn + gr] = vp * meta_cur.x;  // q_vec = kn*norm
    }
}

// ---------------- tmp = read @ rp_w^T + rp_b ---------------------------------
__global__ void __launch_bounds__(128) readrp_kernel(
    const float* __restrict__ rp_w, const float* __restrict__ rp_b)
{
    __shared__ float s_r[128];
    const int b = blockIdx.x;
    s_r[threadIdx.x] = g_read[b * Hn + threadIdx.x];
    __syncthreads();
    const int n = threadIdx.x;
    const float* wrow = rp_w + (size_t)n * Hn;
    float a0 = 0.f, a1 = 0.f, a2 = 0.f, a3 = 0.f;
#pragma unroll 8
    for (int j = 0; j < 128; j += 4) {
        a0 = fmaf(s_r[j + 0], wrow[j + 0], a0);
        a1 = fmaf(s_r[j + 1], wrow[j + 1], a1);
        a2 = fmaf(s_r[j + 2], wrow[j + 2], a2);
        a3 = fmaf(s_r[j + 3], wrow[j + 3], a3);
    }
    g_tmp[b * Hn + n] = (a0 + a1) + (a2 + a3) + rp_b[n];
}

// ---------------- logits ------------------------------------------------------
__global__ void __launch_bounds__(256) logits_kernel(
    const float* __restrict__ out_w, const float* __restrict__ out_b,
    float* __restrict__ outp)
{
    __shared__ __align__(16) float s_t[128][64];  // [j][b]
    for (int i = threadIdx.x; i < Bn * Hn; i += 256) {
        int b = i >> 7, j = i & 127;
        s_t[j][b] = g_tmp[i];
    }
    __syncthreads();

    const int v = blockIdx.x * 256 + threadIdx.x;
    const float4* wr = (const float4*)(out_w + (size_t)v * Hn);
    const float ob = out_b[v];
    float4 acc[16];
#pragma unroll
    for (int q = 0; q < 16; ++q) acc[q] = make_float4(ob, ob, ob, ob);

    for (int j4 = 0; j4 < 32; ++j4) {
        float4 w = wr[j4];
        float wj[4] = {w.x, w.y, w.z, w.w};
#pragma unroll
        for (int c = 0; c < 4; ++c) {
            const float4* tp = (const float4*)s_t[j4 * 4 + c];
#pragma unroll
            for (int q = 0; q < 16; ++q) {
                float4 t = tp[q];
                acc[q].x = fmaf(wj[c], t.x, acc[q].x);
                acc[q].y = fmaf(wj[c], t.y, acc[q].y);
                acc[q].z = fmaf(wj[c], t.z, acc[q].z);
                acc[q].w = fmaf(wj[c], t.w, acc[q].w);
            }
        }
    }
#pragma unroll
    for (int q = 0; q < 16; ++q) {
        outp[(size_t)(q * 4 + 0) * Vn + v] = acc[q].x;
        outp[(size_t)(q * 4 + 1) * Vn + v] = acc[q].y;
        outp[(size_t)(q * 4 + 2) * Vn + v] = acc[q].z;
        outp[(size_t)(q * 4 + 3) * Vn + v] = acc[q].w;
    }
}

// ---------------- launch ------------------------------------------------------
extern "C" void kernel_launch(void* const* d_in, const int* in_sizes, int n_in,
                              void* d_out, int out_size)
{
    const int*   seq    = (const int*)  d_in[0];
    const float* embedW = (const float*)d_in[1];
    const float* ff_w1  = (const float*)d_in[2];
    const float* ff_b1  = (const float*)d_in[3];
    const float* ff_w2  = (const float*)d_in[4];
    const float* ff_b2  = (const float*)d_in[5];
    const float* ln_g   = (const float*)d_in[6];
    const float* ln_b   = (const float*)d_in[7];
    const float* kp_w   = (const float*)d_in[8];
    const float* rp_w   = (const float*)d_in[9];
    const float* rp_b   = (const float*)d_in[10];
    const float* out_w  = (const float*)d_in[11];
    const float* out_b  = (const float*)d_in[12];
    float* outp = (float*)d_out;

    float *p_ff1, *p_x, *p_hn, *p_kt, *p_zero;
    cudaGetSymbolAddress((void**)&p_ff1,  g_ff1);
    cudaGetSymbolAddress((void**)&p_x,    g_x);
    cudaGetSymbolAddress((void**)&p_hn,   g_hn);
    cudaGetSymbolAddress((void**)&p_kt,   g_kt);
    cudaGetSymbolAddress((void**)&p_zero, g_zero);

    // vocab-table pipeline (32000 rows instead of 131072 tokens)
    sgemm_tn<true,  false><<<dim3(Vn / 128, 2), 256>>>(embedW, ff_w1, ff_b1, nullptr, p_ff1, 256, 128);
    sgemm_tn<false, true ><<<dim3(Vn / 128, 1), 256>>>(p_ff1,  ff_w2, ff_b2, embedW,  p_x,   128, 256);
    ln_kernel  <<<Vn / 8, 256>>>(ln_g, ln_b);
    sgemm_tn<false, false><<<dim3(Vn / 128, 1), 256>>>(p_hn,   kp_w,  p_zero, nullptr, p_kt,  128, 128);
    norm_kernel<<<Vn / 8, 256>>>();

    // paired-CTA scan: 2 plain CTAs per batch (128 blocks, single wave)
    scan_kernel<<<Bn * 2, 256>>>(seq);

    // output head
    readrp_kernel<<<Bn, 128>>>(rp_w, rp_b);
    logits_kernel<<<Vn / 256, 256>>>(out_w, out_b, outp);
}